// round 2
// baseline (speedup 1.0000x reference)
#include <cuda_runtime.h>
#include <cstdint>

#define IN_FEAT 256
#define OUT_FEAT 128

// ---------------------------------------------------------------------------
// GEMM: C[M,128] = A[M,256] * B[256,128]   (fp32, register-blocked SIMT)
// BM=128, BN=128, BK=16, 256 threads, 8x8 outputs/thread.
// ---------------------------------------------------------------------------
#define BM 128
#define BK 16

__global__ __launch_bounds__(256) void gemm_kernel(
    const float* __restrict__ A,   // [M, 256]
    const float* __restrict__ B,   // [256, 128]
    float* __restrict__ C,         // [M, 128]
    int M)
{
    __shared__ float Ask[BK][BM + 4];   // transposed A tile, padded (stride 132 floats, 16B aligned)
    __shared__ float Bs[BK][OUT_FEAT];

    const int tid = threadIdx.x;
    const int m0  = blockIdx.x * BM;
    const int tx  = tid & 15;    // col group: cols tx*8 .. tx*8+7
    const int ty  = tid >> 4;    // row group: rows ty*8 .. ty*8+7

    float acc[8][8];
#pragma unroll
    for (int i = 0; i < 8; i++)
#pragma unroll
        for (int j = 0; j < 8; j++) acc[i][j] = 0.0f;

    for (int k0 = 0; k0 < IN_FEAT; k0 += BK) {
        // --- load A tile (128 rows x 16 k) transposed into smem ---
#pragma unroll
        for (int t = 0; t < 2; t++) {
            int id  = tid + t * 256;     // 0..511 float4 ids
            int row = id >> 2;           // 0..127
            int kp  = (id & 3) * 4;      // 0,4,8,12
            float4 a;
            int gr = m0 + row;
            if (gr < M) {
                a = *reinterpret_cast<const float4*>(A + (size_t)gr * IN_FEAT + k0 + kp);
            } else {
                a = make_float4(0.f, 0.f, 0.f, 0.f);
            }
            Ask[kp + 0][row] = a.x;
            Ask[kp + 1][row] = a.y;
            Ask[kp + 2][row] = a.z;
            Ask[kp + 3][row] = a.w;
        }
        // --- load B tile (16 x 128, contiguous in global) ---
        {
            const float4* Bg  = reinterpret_cast<const float4*>(B + k0 * OUT_FEAT);
            float4*       Bs4 = reinterpret_cast<float4*>(&Bs[0][0]);
            Bs4[tid]       = Bg[tid];
            Bs4[tid + 256] = Bg[tid + 256];
        }
        __syncthreads();

#pragma unroll
        for (int k = 0; k < BK; k++) {
            float4 a0 = *reinterpret_cast<float4*>(&Ask[k][ty * 8]);
            float4 a1 = *reinterpret_cast<float4*>(&Ask[k][ty * 8 + 4]);
            float4 b0 = *reinterpret_cast<float4*>(&Bs[k][tx * 8]);
            float4 b1 = *reinterpret_cast<float4*>(&Bs[k][tx * 8 + 4]);
            float ar[8] = {a0.x, a0.y, a0.z, a0.w, a1.x, a1.y, a1.z, a1.w};
            float br[8] = {b0.x, b0.y, b0.z, b0.w, b1.x, b1.y, b1.z, b1.w};
#pragma unroll
            for (int i = 0; i < 8; i++)
#pragma unroll
                for (int j = 0; j < 8; j++)
                    acc[i][j] += ar[i] * br[j];
        }
        __syncthreads();
    }

    // --- epilogue ---
#pragma unroll
    for (int i = 0; i < 8; i++) {
        int gr = m0 + ty * 8 + i;
        if (gr < M) {
            float4 o0 = make_float4(acc[i][0], acc[i][1], acc[i][2], acc[i][3]);
            float4 o1 = make_float4(acc[i][4], acc[i][5], acc[i][6], acc[i][7]);
            float* cp = C + (size_t)gr * OUT_FEAT + tx * 8;
            *reinterpret_cast<float4*>(cp)     = o0;
            *reinterpret_cast<float4*>(cp + 4) = o1;
        }
    }
}

// ---------------------------------------------------------------------------
// SPMM with sorted edge_row: x[r] = sum_{e: row[e]=r} val[e] * femb[col[e]]
// One block (128 threads = 128 output cols) per chunk of 256 edges.
// Segmented reduction in registers: interior segments plain-store, boundary
// segments atomicAdd (x is zeroed beforehand).
// ---------------------------------------------------------------------------
#define ECHUNK 256

__global__ __launch_bounds__(128) void spmm_kernel(
    const int*   __restrict__ erow,
    const int*   __restrict__ ecol,
    const float* __restrict__ eval,
    const float* __restrict__ femb,   // [N, 128]
    float*       __restrict__ x,      // [N, 128], pre-zeroed
    int E)
{
    __shared__ int   srow[ECHUNK];
    __shared__ int   scol[ECHUNK];
    __shared__ float sval[ECHUNK];

    const int base = blockIdx.x * ECHUNK;
    const int n    = min(ECHUNK, E - base);

    for (int i = threadIdx.x; i < n; i += blockDim.x) {
        srow[i] = erow[base + i];
        scol[i] = ecol[base + i];
        sval[i] = eval[base + i];
    }
    __syncthreads();

    const int c = threadIdx.x;   // output column
    float acc  = 0.0f;
    int   cur  = srow[0];
    bool  first = true;

    for (int i = 0; i < n; i += 4) {
        const int cnt = min(4, n - i);
        float v[4];
        // prefetch batch of 4 gathers (MLP=4)
#pragma unroll
        for (int j = 0; j < 4; j++)
            if (j < cnt) v[j] = femb[(size_t)scol[i + j] * OUT_FEAT + c];
#pragma unroll
        for (int j = 0; j < 4; j++) {
            if (j < cnt) {
                int r = srow[i + j];
                if (r != cur) {
                    float* xp = x + (size_t)cur * OUT_FEAT + c;
                    if (first) { atomicAdd(xp, acc); first = false; }
                    else       { *xp = acc; }
                    acc = 0.0f;
                    cur = r;
                }
                acc += sval[i + j] * v[j];
            }
        }
    }
    // trailing segment may continue into the next chunk
    atomicAdd(x + (size_t)cur * OUT_FEAT + c, acc);
}

// ---------------------------------------------------------------------------
// Launch
// ---------------------------------------------------------------------------
extern "C" void kernel_launch(void* const* d_in, const int* in_sizes, int n_in,
                              void* d_out, int out_size)
{
    const float* feat = (const float*)d_in[0];   // [N, 256]
    const int*   erow = (const int*)  d_in[1];   // [E]
    const int*   ecol = (const int*)  d_in[2];   // [E]
    const float* eval = (const float*)d_in[3];   // [E]
    const float* W    = (const float*)d_in[4];   // [256, 128]

    const int M = in_sizes[0] / IN_FEAT;         // 100000
    const int E = in_sizes[1];                   // 3200000

    float* femb = (float*)d_out;                     // first output
    float* x    = femb + (size_t)M * OUT_FEAT;       // second output

    // zero the segment-sum output (atomics accumulate into it)
    cudaMemsetAsync(x, 0, (size_t)M * OUT_FEAT * sizeof(float), 0);

    gemm_kernel<<<(M + BM - 1) / BM, 256>>>(feat, W, femb, M);
    spmm_kernel<<<(E + ECHUNK - 1) / ECHUNK, 128>>>(erow, ecol, eval, femb, x, E);
}